// round 11
// baseline (speedup 1.0000x reference)
#include <cuda_runtime.h>
#include <cuda_bf16.h>
#include <math.h>

#define D     256
#define S     32
#define CTX   33
#define MAXN  20000
#define MAXP  20032      // padded row count (multiple of 64)
#define MTILE 64

typedef unsigned long long ull;

// ---- device scratch ----
__device__ __align__(16) float g_q[D];                 // Wk^T bq
__device__ __align__(16) float g_Qt[MAXN * D];
// X operands pre-split to bf16 hi/lo (padded rows read-safe, zero-init)
__device__ __align__(16) __nv_bfloat16 g_X0h[MAXP * D];
__device__ __align__(16) __nv_bfloat16 g_X0l[MAXP * D];
__device__ __align__(16) __nv_bfloat16 g_X1h[MAXP * D];
__device__ __align__(16) __nv_bfloat16 g_X1l[MAXP * D];
// B matrices, bf16 hi/lo splits, [k][n] row-major
__device__ __align__(16) __nv_bfloat16 g_B0h[D * D];   // split of Wq^T Wk
__device__ __align__(16) __nv_bfloat16 g_B0l[D * D];
__device__ __align__(16) __nv_bfloat16 g_B1h[D * D];   // split of Wv^T
__device__ __align__(16) __nv_bfloat16 g_B1l[D * D];

__device__ __forceinline__ void bsplit(float x, __nv_bfloat16& h, __nv_bfloat16& l) {
    h = __float2bfloat16(x);
    l = __float2bfloat16(x - __bfloat162float(h));
}
__device__ __forceinline__ unsigned sptr(const void* p) {
    return (unsigned)__cvta_generic_to_shared(p);
}
__device__ __forceinline__ void cp16(void* smem_dst, const void* gsrc) {
    unsigned s = sptr(smem_dst);
    asm volatile("cp.async.cg.shared.global [%0], [%1], 16;" :: "r"(s), "l"(gsrc));
}
__device__ __forceinline__ unsigned packbf(__nv_bfloat16 a, __nv_bfloat16 b) {
    return (unsigned)__bfloat16_as_ushort(a) | ((unsigned)__bfloat16_as_ushort(b) << 16);
}

#define MMA_BF16(ac, A, B0, B1)                                              \
    asm volatile("mma.sync.aligned.m16n8k16.row.col.f32.bf16.bf16.f32 "      \
                 "{%0,%1,%2,%3},{%4,%5,%6,%7},{%8,%9},{%0,%1,%2,%3};"        \
                 : "+f"(ac[0]), "+f"(ac[1]), "+f"(ac[2]), "+f"(ac[3])        \
                 : "r"(A[0]), "r"(A[1]), "r"(A[2]), "r"(A[3]),               \
                   "r"(B0), "r"(B1))

// ============================================================
// prep: B0 = split(Wq^T Wk), q = Wk^T bq, B1 = split(Wv^T)
// ============================================================
__global__ void prep_kernel(const float* __restrict__ Wq,
                            const float* __restrict__ bq,
                            const float* __restrict__ Wk,
                            const float* __restrict__ Wv)
{
    __shared__ __align__(16) float sv[D];
    int b = blockIdx.x;
    int t = threadIdx.x;

    if (b < D) {
        sv[t] = Wq[t * D + b];
        __syncthreads();
        float acc = 0.f;
        #pragma unroll 8
        for (int d = 0; d < D; d++) acc += sv[d] * Wk[d * D + t];
        __nv_bfloat16 h, l;
        bsplit(acc, h, l);
        g_B0h[b * D + t] = h;
        g_B0l[b * D + t] = l;
    } else if (b == D) {
        sv[t] = bq[t];
        __syncthreads();
        float acc = 0.f;
        #pragma unroll 8
        for (int d = 0; d < D; d++) acc += sv[d] * Wk[d * D + t];
        g_q[t] = acc;
    } else {
        int dd = b - (D + 1);
        float v = Wv[dd * D + t];
        __nv_bfloat16 h, l;
        bsplit(v, h, l);
        g_B1h[t * D + dd] = h;
        g_B1l[t * D + dd] = l;
    }
}

// ============================================================
// xsplit: gather feat[node_ids] and write bf16 hi/lo splits.
// One thread = 4 floats.
// ============================================================
__global__ __launch_bounds__(256)
void xsplit_kernel(const int* __restrict__ node_ids,
                   const float* __restrict__ feat,
                   int N)
{
    int idx = blockIdx.x * 256 + threadIdx.x;
    int row = idx >> 6;            // D/4 = 64 groups per row
    if (row >= N) return;
    int col = (idx & 63) * 4;
    float4 v = *(const float4*)(feat + (size_t)node_ids[row] * D + col);
    __nv_bfloat16 h0, h1, h2, h3, l0, l1, l2, l3;
    bsplit(v.x, h0, l0); bsplit(v.y, h1, l1);
    bsplit(v.z, h2, l2); bsplit(v.w, h3, l3);
    uint2 ph = {packbf(h0, h1), packbf(h2, h3)};
    uint2 pl = {packbf(l0, l1), packbf(l2, l3)};
    *(uint2*)(g_X0h + (size_t)row * D + col) = ph;
    *(uint2*)(g_X0l + (size_t)row * D + col) = pl;
}

// ============================================================
// Tensor-core GEMM, bf16-split 3-MMA compensation.
// A arrives PRE-SPLIT from global -> cp.async straight into
// LDSM-ready smem. One barrier per chunk, no conversion stage.
// Warp layout: mg = warp&1 (32 rows), nq = warp>>1 (64 cols).
// MODE 0: A = g_X0*, B = B0, bias = g_q            -> g_Qt
// MODE 1: A = g_X1*, B = B1, bias = bv, tanh+norm  -> out
// ============================================================
template <int MODE>
__global__ __launch_bounds__(256, 2)
void mma_gemm(const float* __restrict__ bias_in,
              float* __restrict__ outp,
              int N)
{
    __shared__ __align__(16) __nv_bfloat16 sBh[2][16 * 256];  // swizzled
    __shared__ __align__(16) __nv_bfloat16 sBl[2][16 * 256];
    __shared__ __align__(16) __nv_bfloat16 sAh[2][64 * 24];   // stride 24
    __shared__ __align__(16) __nv_bfloat16 sAl[2][64 * 24];
    __shared__ float sRS[64][4];

    const int tid  = threadIdx.x;
    const int lane = tid & 31;
    const int warp = tid >> 5;
    const int mg   = warp & 1;
    const int nq   = warp >> 1;
    const int m0   = blockIdx.x * MTILE;

    const __nv_bfloat16* gBh = (MODE == 0) ? g_B0h : g_B1h;
    const __nv_bfloat16* gBl = (MODE == 0) ? g_B0l : g_B1l;
    const __nv_bfloat16* gXh = (MODE == 0) ? g_X0h : g_X1h;
    const __nv_bfloat16* gXl = (MODE == 0) ? g_X0l : g_X1l;

    // per-thread A-copy assignment: 128 (row,half) slots per split
    const int asp   = tid >> 7;            // 0 = hi, 1 = lo
    const int ar    = (tid & 127) >> 1;    // row 0..63
    const int ahalf = tid & 1;             // 16B half

    auto issue = [&](int buf, int c) {
        #pragma unroll
        for (int j = 0; j < 2; j++) {
            int gi = tid + j * 256;
            int k  = gi >> 5, cn = gi & 31;
            int dc = cn ^ (k & 7);
            cp16(&sBh[buf][k * 256 + dc * 8], gBh + c * 4096 + k * 256 + cn * 8);
            cp16(&sBl[buf][k * 256 + dc * 8], gBl + c * 4096 + k * 256 + cn * 8);
        }
        const __nv_bfloat16* src = (asp ? gXl : gXh)
                                   + (size_t)(m0 + ar) * D + c * 16 + ahalf * 8;
        __nv_bfloat16* dst = (asp ? sAl[buf] : sAh[buf]) + ar * 24 + ahalf * 8;
        cp16(dst, src);
        asm volatile("cp.async.commit_group;");
    };

    float acc[2][8][4];
    #pragma unroll
    for (int mt = 0; mt < 2; mt++)
        #pragma unroll
        for (int t = 0; t < 8; t++)
            #pragma unroll
            for (int j = 0; j < 4; j++) acc[mt][t][j] = 0.f;

    issue(0, 0);

    const int arow = lane & 15, asel = (lane >> 4) & 1;
    const int krow = lane & 15, bsel = (lane >> 4) & 1;

    #pragma unroll 1
    for (int c = 0; c < 16; c++) {
        int buf = c & 1;
        asm volatile("cp.async.wait_group 0;");
        __syncthreads();
        if (c < 15) issue(buf ^ 1, c + 1);

        // A fragments for 2 m-tiles, hi/lo (layout identical to R10)
        unsigned ah[2][4], al[2][4];
        #pragma unroll
        for (int mt = 0; mt < 2; mt++) {
            unsigned addr = sptr(&sAh[buf][(mg * 32 + mt * 16 + arow) * 24 + asel * 8]);
            asm volatile("ldmatrix.sync.aligned.m8n8.x4.shared.b16 {%0,%1,%2,%3},[%4];"
                         : "=r"(ah[mt][0]), "=r"(ah[mt][1]), "=r"(ah[mt][2]), "=r"(ah[mt][3]) : "r"(addr));
            addr = sptr(&sAl[buf][(mg * 32 + mt * 16 + arow) * 24 + asel * 8]);
            asm volatile("ldmatrix.sync.aligned.m8n8.x4.shared.b16 {%0,%1,%2,%3},[%4];"
                         : "=r"(al[mt][0]), "=r"(al[mt][1]), "=r"(al[mt][2]), "=r"(al[mt][3]) : "r"(addr));
        }

        #pragma unroll
        for (int p = 0; p < 4; p++) {
            int cn = nq * 8 + p * 2 + bsel;
            int bofs = krow * 256 + ((cn ^ (krow & 7)) << 3);
            unsigned bh0, bh1, bh2, bh3, bl0, bl1, bl2, bl3;
            unsigned addr = sptr(&sBh[buf][bofs]);
            asm volatile("ldmatrix.sync.aligned.m8n8.x4.trans.shared.b16 {%0,%1,%2,%3},[%4];"
                         : "=r"(bh0), "=r"(bh1), "=r"(bh2), "=r"(bh3) : "r"(addr));
            addr = sptr(&sBl[buf][bofs]);
            asm volatile("ldmatrix.sync.aligned.m8n8.x4.trans.shared.b16 {%0,%1,%2,%3},[%4];"
                         : "=r"(bl0), "=r"(bl1), "=r"(bl2), "=r"(bl3) : "r"(addr));

            #pragma unroll
            for (int mt = 0; mt < 2; mt++) {
                MMA_BF16(acc[mt][2 * p],     ah[mt], bh0, bh1);
                MMA_BF16(acc[mt][2 * p],     ah[mt], bl0, bl1);
                MMA_BF16(acc[mt][2 * p],     al[mt], bh0, bh1);
                MMA_BF16(acc[mt][2 * p + 1], ah[mt], bh2, bh3);
                MMA_BF16(acc[mt][2 * p + 1], ah[mt], bl2, bl3);
                MMA_BF16(acc[mt][2 * p + 1], al[mt], bh2, bh3);
            }
        }
        __syncthreads();
    }

    // ---- epilogue (unchanged from R10) ----
    const float* bias = (MODE == 0) ? g_q : bias_in;
    const int g   = lane >> 2;
    const int tig = lane & 3;

    #pragma unroll
    for (int mt = 0; mt < 2; mt++)
        #pragma unroll
        for (int t = 0; t < 8; t++) {
            int col = nq * 64 + t * 8 + tig * 2;
            float bx = bias[col], by = bias[col + 1];
            acc[mt][t][0] += bx; acc[mt][t][1] += by;
            acc[mt][t][2] += bx; acc[mt][t][3] += by;
        }

    if (MODE == 0) {
        #pragma unroll
        for (int mt = 0; mt < 2; mt++) {
            int row0 = m0 + mg * 32 + mt * 16 + g;
            int row1 = row0 + 8;
            #pragma unroll
            for (int t = 0; t < 8; t++) {
                int col = nq * 64 + t * 8 + tig * 2;
                if (row0 < N) {
                    float2 o = {acc[mt][t][0], acc[mt][t][1]};
                    *(float2*)(g_Qt + (size_t)row0 * D + col) = o;
                }
                if (row1 < N) {
                    float2 o = {acc[mt][t][2], acc[mt][t][3]};
                    *(float2*)(g_Qt + (size_t)row1 * D + col) = o;
                }
            }
        }
    } else {
        #pragma unroll
        for (int mt = 0; mt < 2; mt++) {
            float s0 = 0.f, s1 = 0.f;
            #pragma unroll
            for (int t = 0; t < 8; t++) {
                #pragma unroll
                for (int j = 0; j < 4; j++) acc[mt][t][j] = tanhf(acc[mt][t][j]);
                s0 += acc[mt][t][0] * acc[mt][t][0] + acc[mt][t][1] * acc[mt][t][1];
                s1 += acc[mt][t][2] * acc[mt][t][2] + acc[mt][t][3] * acc[mt][t][3];
            }
            s0 += __shfl_xor_sync(0xFFFFFFFFu, s0, 1);
            s0 += __shfl_xor_sync(0xFFFFFFFFu, s0, 2);
            s1 += __shfl_xor_sync(0xFFFFFFFFu, s1, 1);
            s1 += __shfl_xor_sync(0xFFFFFFFFu, s1, 2);
            if (tig == 0) {
                sRS[mg * 32 + mt * 16 + g][nq]     = s0;
                sRS[mg * 32 + mt * 16 + g + 8][nq] = s1;
            }
        }
        __syncthreads();
        #pragma unroll
        for (int mt = 0; mt < 2; mt++) {
            int r0 = mg * 32 + mt * 16 + g;
            int r1 = r0 + 8;
            float t0 = sRS[r0][0] + sRS[r0][1] + sRS[r0][2] + sRS[r0][3];
            float t1 = sRS[r1][0] + sRS[r1][1] + sRS[r1][2] + sRS[r1][3];
            float inv0 = 1.f / fmaxf(sqrtf(t0), 1e-12f);
            float inv1 = 1.f / fmaxf(sqrtf(t1), 1e-12f);
            int row0 = m0 + r0, row1 = m0 + r1;
            #pragma unroll
            for (int t = 0; t < 8; t++) {
                int col = nq * 64 + t * 8 + tig * 2;
                if (row0 < N) {
                    float2 o = {acc[mt][t][0] * inv0, acc[mt][t][1] * inv0};
                    *(float2*)(outp + (size_t)row0 * D + col) = o;
                }
                if (row1 < N) {
                    float2 o = {acc[mt][t][2] * inv1, acc[mt][t][3] * inv1};
                    *(float2*)(outp + (size_t)row1 * D + col) = o;
                }
            }
        }
    }
}

// ============================================================
// attention: one warp per node, online softmax, 2-deep prefetch.
// Output written PRE-SPLIT (bf16 hi/lo) for gemm<1>.
// ============================================================
__global__ __launch_bounds__(256)
void attn_kernel(const int* __restrict__ node_ids,
                 const int* __restrict__ neigh_ids,
                 const float* __restrict__ feat,
                 int N)
{
    const int warp = threadIdx.x >> 5;
    const int lane = threadIdx.x & 31;
    const int n    = blockIdx.x * 8 + warp;
    if (n >= N) return;

    const float4* qt4 = (const float4*)(g_Qt + (size_t)n * D);
    float4 qa = qt4[lane];
    float4 qb = qt4[32 + lane];

    int id_l = neigh_ids[(size_t)n * S + lane];

    const float4* feat4 = (const float4*)feat;
    // preload rows 0 (self) and 1 (neighbor 0)
    const float4* p0 = feat4 + (size_t)node_ids[n] * 64;
    float4 ca = p0[lane];
    float4 cb = p0[32 + lane];
    int id1 = __shfl_sync(0xFFFFFFFFu, id_l, 0);
    const float4* p1 = feat4 + (size_t)id1 * 64;
    float4 na = p1[lane];
    float4 nb = p1[32 + lane];

    float m = -3.0e38f, s = 0.f;
    float4 aa = {0.f, 0.f, 0.f, 0.f};
    float4 ab = {0.f, 0.f, 0.f, 0.f};

    #pragma unroll 1
    for (int k = 0; k < CTX; k++) {
        float4 pa, pb;
        if (k + 2 <= S) {
            int idn = __shfl_sync(0xFFFFFFFFu, id_l, k + 1);
            const float4* pn = feat4 + (size_t)idn * 64;
            pa = pn[lane];
            pb = pn[32 + lane];
        }
        float d = ca.x * qa.x + ca.y * qa.y + ca.z * qa.z + ca.w * qa.w
                + cb.x * qb.x + cb.y * qb.y + cb.z * qb.z + cb.w * qb.w;
        #pragma unroll
        for (int o = 16; o > 0; o >>= 1)
            d += __shfl_xor_sync(0xFFFFFFFFu, d, o);

        float mn = fmaxf(m, d);
        float sc = __expf(m - mn);
        float e  = __expf(d - mn);
        s = s * sc + e;
        aa.x = aa.x * sc + e * ca.x;  aa.y = aa.y * sc + e * ca.y;
        aa.z = aa.z * sc + e * ca.z;  aa.w = aa.w * sc + e * ca.w;
        ab.x = ab.x * sc + e * cb.x;  ab.y = ab.y * sc + e * cb.y;
        ab.z = ab.z * sc + e * cb.z;  ab.w = ab.w * sc + e * cb.w;
        m = mn;
        ca = na; cb = nb;
        na = pa; nb = pb;
    }

    float inv = 1.f / s;
    float v[8] = {aa.x * inv, aa.y * inv, aa.z * inv, aa.w * inv,
                  ab.x * inv, ab.y * inv, ab.z * inv, ab.w * inv};

    // write bf16 hi/lo splits directly (same byte volume as fp32)
    __nv_bfloat16 h[8], l[8];
    #pragma unroll
    for (int j = 0; j < 8; j++) bsplit(v[j], h[j], l[j]);
    uint2 ph0 = {packbf(h[0], h[1]), packbf(h[2], h[3])};
    uint2 ph1 = {packbf(h[4], h[5]), packbf(h[6], h[7])};
    uint2 pl0 = {packbf(l[0], l[1]), packbf(l[2], l[3])};
    uint2 pl1 = {packbf(l[4], l[5]), packbf(l[6], l[7])};
    size_t base = (size_t)n * D;
    *(uint2*)(g_X1h + base + lane * 4)       = ph0;
    *(uint2*)(g_X1h + base + 128 + lane * 4) = ph1;
    *(uint2*)(g_X1l + base + lane * 4)       = pl0;
    *(uint2*)(g_X1l + base + 128 + lane * 4) = pl1;
}

// ============================================================
// inputs: node_ids, neigh_ids, feat_table, Wq, bq, Wk, bk, Wv, bv
// (bk only enters softmax-invariant terms -> provably unused)
// ============================================================
extern "C" void kernel_launch(void* const* d_in, const int* in_sizes, int n_in,
                              void* d_out, int out_size)
{
    const int*   node_ids  = (const int*)d_in[0];
    const int*   neigh_ids = (const int*)d_in[1];
    const float* feat      = (const float*)d_in[2];
    const float* Wq        = (const float*)d_in[3];
    const float* bq        = (const float*)d_in[4];
    const float* Wk        = (const float*)d_in[5];
    const float* Wv        = (const float*)d_in[7];
    const float* bv        = (const float*)d_in[8];
    float*       out       = (float*)d_out;

    int N = in_sizes[0];
    if (N > MAXN) N = MAXN;

    int gblocks = (N + MTILE - 1) / MTILE;
    int ablocks = (N + 7) / 8;
    int xblocks = (N * 64 + 255) / 256;

    prep_kernel<<<2 * D + 1, 256>>>(Wq, bq, Wk, Wv);
    xsplit_kernel<<<xblocks, 256>>>(node_ids, feat, N);
    mma_gemm<0><<<gblocks, 256>>>(nullptr, nullptr, N);
    attn_kernel<<<ablocks, 256>>>(node_ids, neigh_ids, feat, N);
    mma_gemm<1><<<gblocks, 256>>>(bv, out, N);
}

// round 13
// speedup vs baseline: 1.0716x; 1.0716x over previous
#include <cuda_runtime.h>
#include <cuda_bf16.h>
#include <math.h>

#define D     256
#define S     32
#define CTX   33
#define MAXN  20000
#define MAXP  20032      // padded row count (multiple of 64)
#define MTILE 64

typedef unsigned long long ull;

// ---- device scratch ----
__device__ __align__(16) float g_q[D];                 // Wk^T bq
__device__ __align__(16) float g_Qt[MAXN * D];
// X operands pre-split to bf16 hi/lo
__device__ __align__(16) __nv_bfloat16 g_X0h[MAXP * D];
__device__ __align__(16) __nv_bfloat16 g_X0l[MAXP * D];
__device__ __align__(16) __nv_bfloat16 g_X1h[MAXP * D];
__device__ __align__(16) __nv_bfloat16 g_X1l[MAXP * D];
// B matrices, bf16 hi/lo splits, [k][n] row-major
__device__ __align__(16) __nv_bfloat16 g_B0h[D * D];   // split of Wq^T Wk
__device__ __align__(16) __nv_bfloat16 g_B0l[D * D];
__device__ __align__(16) __nv_bfloat16 g_B1h[D * D];   // split of Wv^T
__device__ __align__(16) __nv_bfloat16 g_B1l[D * D];

__device__ __forceinline__ void bsplit(float x, __nv_bfloat16& h, __nv_bfloat16& l) {
    h = __float2bfloat16(x);
    l = __float2bfloat16(x - __bfloat162float(h));
}
__device__ __forceinline__ unsigned sptr(const void* p) {
    return (unsigned)__cvta_generic_to_shared(p);
}
__device__ __forceinline__ void cp16(void* smem_dst, const void* gsrc) {
    unsigned s = sptr(smem_dst);
    asm volatile("cp.async.cg.shared.global [%0], [%1], 16;" :: "r"(s), "l"(gsrc));
}
__device__ __forceinline__ unsigned packbf(__nv_bfloat16 a, __nv_bfloat16 b) {
    return (unsigned)__bfloat16_as_ushort(a) | ((unsigned)__bfloat16_as_ushort(b) << 16);
}

#define MMA_BF16(ac, A, B0, B1)                                              \
    asm volatile("mma.sync.aligned.m16n8k16.row.col.f32.bf16.bf16.f32 "      \
                 "{%0,%1,%2,%3},{%4,%5,%6,%7},{%8,%9},{%0,%1,%2,%3};"        \
                 : "+f"(ac[0]), "+f"(ac[1]), "+f"(ac[2]), "+f"(ac[3])        \
                 : "r"(A[0]), "r"(A[1]), "r"(A[2]), "r"(A[3]),               \
                   "r"(B0), "r"(B1))

// ============================================================
// prep + xsplit merged (independent work, concurrent blocks)
// ============================================================
__global__ void prep_xsplit_kernel(const int* __restrict__ node_ids,
                                   const float* __restrict__ feat,
                                   const float* __restrict__ Wq,
                                   const float* __restrict__ bq,
                                   const float* __restrict__ Wk,
                                   const float* __restrict__ Wv,
                                   int N, int xblocks)
{
    __shared__ __align__(16) float sv[D];
    int t = threadIdx.x;

    if (blockIdx.x < (unsigned)xblocks) {
        int idx = blockIdx.x * 256 + t;
        int row = idx >> 6;
        if (row >= N) return;
        int col = (idx & 63) * 4;
        float4 v = *(const float4*)(feat + (size_t)node_ids[row] * D + col);
        __nv_bfloat16 h0, h1, h2, h3, l0, l1, l2, l3;
        bsplit(v.x, h0, l0); bsplit(v.y, h1, l1);
        bsplit(v.z, h2, l2); bsplit(v.w, h3, l3);
        uint2 ph = {packbf(h0, h1), packbf(h2, h3)};
        uint2 pl = {packbf(l0, l1), packbf(l2, l3)};
        *(uint2*)(g_X0h + (size_t)row * D + col) = ph;
        *(uint2*)(g_X0l + (size_t)row * D + col) = pl;
        return;
    }

    int b = blockIdx.x - xblocks;
    if (b < D) {
        sv[t] = Wq[t * D + b];
        __syncthreads();
        float acc = 0.f;
        #pragma unroll 8
        for (int d = 0; d < D; d++) acc += sv[d] * Wk[d * D + t];
        __nv_bfloat16 h, l;
        bsplit(acc, h, l);
        g_B0h[b * D + t] = h;
        g_B0l[b * D + t] = l;
    } else if (b == D) {
        sv[t] = bq[t];
        __syncthreads();
        float acc = 0.f;
        #pragma unroll 8
        for (int d = 0; d < D; d++) acc += sv[d] * Wk[d * D + t];
        g_q[t] = acc;
    } else {
        int dd = b - (D + 1);
        float v = Wv[dd * D + t];
        __nv_bfloat16 h, l;
        bsplit(v, h, l);
        g_B1h[t * D + dd] = h;
        g_B1l[t * D + dd] = l;
    }
}

// ============================================================
// Tensor-core GEMM, bf16-split 3-MMA compensation.
// A pre-split in global; cp.async double-buffered; ONE barrier/chunk.
// MODE 0: A = g_X0*, B = B0, bias = g_q            -> g_Qt
// MODE 1: A = g_X1*, B = B1, bias = bv, tanh+norm  -> out
// ============================================================
template <int MODE>
__global__ __launch_bounds__(256, 2)
void mma_gemm(const float* __restrict__ bias_in,
              float* __restrict__ outp,
              int N)
{
    __shared__ __align__(16) __nv_bfloat16 sBh[2][16 * 256];
    __shared__ __align__(16) __nv_bfloat16 sBl[2][16 * 256];
    __shared__ __align__(16) __nv_bfloat16 sAh[2][64 * 24];
    __shared__ __align__(16) __nv_bfloat16 sAl[2][64 * 24];
    __shared__ float sRS[64][4];

    const int tid  = threadIdx.x;
    const int lane = tid & 31;
    const int warp = tid >> 5;
    const int mg   = warp & 1;
    const int nq   = warp >> 1;
    const int m0   = blockIdx.x * MTILE;

    const __nv_bfloat16* gBh = (MODE == 0) ? g_B0h : g_B1h;
    const __nv_bfloat16* gBl = (MODE == 0) ? g_B0l : g_B1l;
    const __nv_bfloat16* gXh = (MODE == 0) ? g_X0h : g_X1h;
    const __nv_bfloat16* gXl = (MODE == 0) ? g_X0l : g_X1l;

    const int asp   = tid >> 7;
    const int ar    = (tid & 127) >> 1;
    const int ahalf = tid & 1;

    auto issue = [&](int buf, int c) {
        #pragma unroll
        for (int j = 0; j < 2; j++) {
            int gi = tid + j * 256;
            int k  = gi >> 5, cn = gi & 31;
            int dc = cn ^ (k & 7);
            cp16(&sBh[buf][k * 256 + dc * 8], gBh + c * 4096 + k * 256 + cn * 8);
            cp16(&sBl[buf][k * 256 + dc * 8], gBl + c * 4096 + k * 256 + cn * 8);
        }
        const __nv_bfloat16* src = (asp ? gXl : gXh)
                                   + (size_t)(m0 + ar) * D + c * 16 + ahalf * 8;
        __nv_bfloat16* dst = (asp ? sAl[buf] : sAh[buf]) + ar * 24 + ahalf * 8;
        cp16(dst, src);
        asm volatile("cp.async.commit_group;");
    };

    float acc[2][8][4];
    #pragma unroll
    for (int mt = 0; mt < 2; mt++)
        #pragma unroll
        for (int t = 0; t < 8; t++)
            #pragma unroll
            for (int j = 0; j < 4; j++) acc[mt][t][j] = 0.f;

    issue(0, 0);

    const int arow = lane & 15, asel = (lane >> 4) & 1;
    const int krow = lane & 15, bsel = (lane >> 4) & 1;

    #pragma unroll 1
    for (int c = 0; c < 16; c++) {
        int buf = c & 1;
        asm volatile("cp.async.wait_group 0;");
        __syncthreads();          // single barrier per chunk
        if (c < 15) issue(buf ^ 1, c + 1);

        unsigned ah[2][4], al[2][4];
        #pragma unroll
        for (int mt = 0; mt < 2; mt++) {
            unsigned addr = sptr(&sAh[buf][(mg * 32 + mt * 16 + arow) * 24 + asel * 8]);
            asm volatile("ldmatrix.sync.aligned.m8n8.x4.shared.b16 {%0,%1,%2,%3},[%4];"
                         : "=r"(ah[mt][0]), "=r"(ah[mt][1]), "=r"(ah[mt][2]), "=r"(ah[mt][3]) : "r"(addr));
            addr = sptr(&sAl[buf][(mg * 32 + mt * 16 + arow) * 24 + asel * 8]);
            asm volatile("ldmatrix.sync.aligned.m8n8.x4.shared.b16 {%0,%1,%2,%3},[%4];"
                         : "=r"(al[mt][0]), "=r"(al[mt][1]), "=r"(al[mt][2]), "=r"(al[mt][3]) : "r"(addr));
        }

        #pragma unroll
        for (int p = 0; p < 4; p++) {
            int cn = nq * 8 + p * 2 + bsel;
            int bofs = krow * 256 + ((cn ^ (krow & 7)) << 3);
            unsigned bh0, bh1, bh2, bh3, bl0, bl1, bl2, bl3;
            unsigned addr = sptr(&sBh[buf][bofs]);
            asm volatile("ldmatrix.sync.aligned.m8n8.x4.trans.shared.b16 {%0,%1,%2,%3},[%4];"
                         : "=r"(bh0), "=r"(bh1), "=r"(bh2), "=r"(bh3) : "r"(addr));
            addr = sptr(&sBl[buf][bofs]);
            asm volatile("ldmatrix.sync.aligned.m8n8.x4.trans.shared.b16 {%0,%1,%2,%3},[%4];"
                         : "=r"(bl0), "=r"(bl1), "=r"(bl2), "=r"(bl3) : "r"(addr));

            #pragma unroll
            for (int mt = 0; mt < 2; mt++) {
                MMA_BF16(acc[mt][2 * p],     ah[mt], bh0, bh1);
                MMA_BF16(acc[mt][2 * p],     ah[mt], bl0, bl1);
                MMA_BF16(acc[mt][2 * p],     al[mt], bh0, bh1);
                MMA_BF16(acc[mt][2 * p + 1], ah[mt], bh2, bh3);
                MMA_BF16(acc[mt][2 * p + 1], ah[mt], bl2, bl3);
                MMA_BF16(acc[mt][2 * p + 1], al[mt], bh2, bh3);
            }
        }
    }

    // ---- epilogue ----
    const float* bias = (MODE == 0) ? g_q : bias_in;
    const int g   = lane >> 2;
    const int tig = lane & 3;

    #pragma unroll
    for (int mt = 0; mt < 2; mt++)
        #pragma unroll
        for (int t = 0; t < 8; t++) {
            int col = nq * 64 + t * 8 + tig * 2;
            float bx = bias[col], by = bias[col + 1];
            acc[mt][t][0] += bx; acc[mt][t][1] += by;
            acc[mt][t][2] += bx; acc[mt][t][3] += by;
        }

    if (MODE == 0) {
        #pragma unroll
        for (int mt = 0; mt < 2; mt++) {
            int row0 = m0 + mg * 32 + mt * 16 + g;
            int row1 = row0 + 8;
            #pragma unroll
            for (int t = 0; t < 8; t++) {
                int col = nq * 64 + t * 8 + tig * 2;
                if (row0 < N) {
                    float2 o = {acc[mt][t][0], acc[mt][t][1]};
                    *(float2*)(g_Qt + (size_t)row0 * D + col) = o;
                }
                if (row1 < N) {
                    float2 o = {acc[mt][t][2], acc[mt][t][3]};
                    *(float2*)(g_Qt + (size_t)row1 * D + col) = o;
                }
            }
        }
    } else {
        #pragma unroll
        for (int mt = 0; mt < 2; mt++) {
            float s0 = 0.f, s1 = 0.f;
            #pragma unroll
            for (int t = 0; t < 8; t++) {
                #pragma unroll
                for (int j = 0; j < 4; j++) acc[mt][t][j] = tanhf(acc[mt][t][j]);
                s0 += acc[mt][t][0] * acc[mt][t][0] + acc[mt][t][1] * acc[mt][t][1];
                s1 += acc[mt][t][2] * acc[mt][t][2] + acc[mt][t][3] * acc[mt][t][3];
            }
            s0 += __shfl_xor_sync(0xFFFFFFFFu, s0, 1);
            s0 += __shfl_xor_sync(0xFFFFFFFFu, s0, 2);
            s1 += __shfl_xor_sync(0xFFFFFFFFu, s1, 1);
            s1 += __shfl_xor_sync(0xFFFFFFFFu, s1, 2);
            if (tig == 0) {
                sRS[mg * 32 + mt * 16 + g][nq]     = s0;
                sRS[mg * 32 + mt * 16 + g + 8][nq] = s1;
            }
        }
        __syncthreads();
        #pragma unroll
        for (int mt = 0; mt < 2; mt++) {
            int r0 = mg * 32 + mt * 16 + g;
            int r1 = r0 + 8;
            float t0 = sRS[r0][0] + sRS[r0][1] + sRS[r0][2] + sRS[r0][3];
            float t1 = sRS[r1][0] + sRS[r1][1] + sRS[r1][2] + sRS[r1][3];
            float inv0 = 1.f / fmaxf(sqrtf(t0), 1e-12f);
            float inv1 = 1.f / fmaxf(sqrtf(t1), 1e-12f);
            int row0 = m0 + r0, row1 = m0 + r1;
            #pragma unroll
            for (int t = 0; t < 8; t++) {
                int col = nq * 64 + t * 8 + tig * 2;
                if (row0 < N) {
                    float2 o = {acc[mt][t][0] * inv0, acc[mt][t][1] * inv0};
                    *(float2*)(outp + (size_t)row0 * D + col) = o;
                }
                if (row1 < N) {
                    float2 o = {acc[mt][t][2] * inv1, acc[mt][t][3] * inv1};
                    *(float2*)(outp + (size_t)row1 * D + col) = o;
                }
            }
        }
    }
}

// ============================================================
// attention: one warp per node, PAIRED online softmax.
// Two rows per iteration: interleaved shuffle trees (2x ILP on
// the reduction chain), merged rescale (3 exps / pair), 4 rows
// of gathers in flight. Output pre-split bf16 hi/lo.
// ============================================================
__global__ __launch_bounds__(256)
void attn_kernel(const int* __restrict__ node_ids,
                 const int* __restrict__ neigh_ids,
                 const float* __restrict__ feat,
                 int N)
{
    const int warp = threadIdx.x >> 5;
    const int lane = threadIdx.x & 31;
    const int n    = blockIdx.x * 8 + warp;
    if (n >= N) return;

    const float4* qt4 = (const float4*)(g_Qt + (size_t)n * D);
    float4 qa = qt4[lane];
    float4 qb = qt4[32 + lane];

    int id_l = neigh_ids[(size_t)n * S + lane];
    const float4* feat4 = (const float4*)feat;

    // row r: 0 = self, r>=1 = neighbor r-1
    auto rowbase = [&](int r) -> const float4* {
        int id = (r == 0) ? node_ids[n] : __shfl_sync(0xFFFFFFFFu, id_l, r - 1);
        return feat4 + (size_t)id * 64;
    };

    // resident pair (c0,c1) + prefetched pair (n0,n1)
    const float4* p;
    p = rowbase(0); float4 c0a = p[lane], c0b = p[32 + lane];
    p = rowbase(1); float4 c1a = p[lane], c1b = p[32 + lane];
    p = rowbase(2); float4 n0a = p[lane], n0b = p[32 + lane];
    p = rowbase(3); float4 n1a = p[lane], n1b = p[32 + lane];

    float m = -3.0e38f, s = 0.f;
    float4 aa = {0.f, 0.f, 0.f, 0.f};
    float4 ab = {0.f, 0.f, 0.f, 0.f};

    #pragma unroll 1
    for (int pr = 0; pr < 16; pr++) {          // pairs cover rows 0..31
        int r2 = 2 * pr + 4, r3 = 2 * pr + 5;
        float4 t0a, t0b, t1a, t1b;
        if (r2 < CTX) { p = rowbase(r2); t0a = p[lane]; t0b = p[32 + lane]; }
        if (r3 < CTX) { p = rowbase(r3); t1a = p[lane]; t1b = p[32 + lane]; }

        float d0 = c0a.x * qa.x + c0a.y * qa.y + c0a.z * qa.z + c0a.w * qa.w
                 + c0b.x * qb.x + c0b.y * qb.y + c0b.z * qb.z + c0b.w * qb.w;
        float d1 = c1a.x * qa.x + c1a.y * qa.y + c1a.z * qa.z + c1a.w * qa.w
                 + c1b.x * qb.x + c1b.y * qb.y + c1b.z * qb.z + c1b.w * qb.w;
        #pragma unroll
        for (int o = 16; o > 0; o >>= 1) {     // two independent trees
            d0 += __shfl_xor_sync(0xFFFFFFFFu, d0, o);
            d1 += __shfl_xor_sync(0xFFFFFFFFu, d1, o);
        }

        float mn = fmaxf(m, fmaxf(d0, d1));
        float sc = __expf(m - mn);
        float e0 = __expf(d0 - mn);
        float e1 = __expf(d1 - mn);
        s = s * sc + e0 + e1;
        aa.x = aa.x * sc + e0 * c0a.x + e1 * c1a.x;
        aa.y = aa.y * sc + e0 * c0a.y + e1 * c1a.y;
        aa.z = aa.z * sc + e0 * c0a.z + e1 * c1a.z;
        aa.w = aa.w * sc + e0 * c0a.w + e1 * c1a.w;
        ab.x = ab.x * sc + e0 * c0b.x + e1 * c1b.x;
        ab.y = ab.y * sc + e0 * c0b.y + e1 * c1b.y;
        ab.z = ab.z * sc + e0 * c0b.z + e1 * c1b.z;
        ab.w = ab.w * sc + e0 * c0b.w + e1 * c1b.w;
        m = mn;
        c0a = n0a; c0b = n0b; c1a = n1a; c1b = n1b;
        n0a = t0a; n0b = t0b; n1a = t1a; n1b = t1b;
    }

    // tail: row 32 is in (c0a, c0b)
    {
        float d = c0a.x * qa.x + c0a.y * qa.y + c0a.z * qa.z + c0a.w * qa.w
                + c0b.x * qb.x + c0b.y * qb.y + c0b.z * qb.z + c0b.w * qb.w;
        #pragma unroll
        for (int o = 16; o > 0; o >>= 1)
            d += __shfl_xor_sync(0xFFFFFFFFu, d, o);
        float mn = fmaxf(m, d);
        float sc = __expf(m - mn);
        float e  = __expf(d - mn);
        s = s * sc + e;
        aa.x = aa.x * sc + e * c0a.x;  aa.y = aa.y * sc + e * c0a.y;
        aa.z = aa.z * sc + e * c0a.z;  aa.w = aa.w * sc + e * c0a.w;
        ab.x = ab.x * sc + e * c0b.x;  ab.y = ab.y * sc + e * c0b.y;
        ab.z = ab.z * sc + e * c0b.z;  ab.w = ab.w * sc + e * c0b.w;
    }

    float inv = 1.f / s;
    float v[8] = {aa.x * inv, aa.y * inv, aa.z * inv, aa.w * inv,
                  ab.x * inv, ab.y * inv, ab.z * inv, ab.w * inv};

    __nv_bfloat16 h[8], l[8];
    #pragma unroll
    for (int j = 0; j < 8; j++) bsplit(v[j], h[j], l[j]);
    uint2 ph0 = {packbf(h[0], h[1]), packbf(h[2], h[3])};
    uint2 ph1 = {packbf(h[4], h[5]), packbf(h[6], h[7])};
    uint2 pl0 = {packbf(l[0], l[1]), packbf(l[2], l[3])};
    uint2 pl1 = {packbf(l[4], l[5]), packbf(l[6], l[7])};
    size_t base = (size_t)n * D;
    *(uint2*)(g_X1h + base + lane * 4)       = ph0;
    *(uint2*)(g_X1h + base + 128 + lane * 4) = ph1;
    *(uint2*)(g_X1l + base + lane * 4)       = pl0;
    *(uint2*)(g_X1l + base + 128 + lane * 4) = pl1;
}

// ============================================================
// inputs: node_ids, neigh_ids, feat_table, Wq, bq, Wk, bk, Wv, bv
// (bk only enters softmax-invariant terms -> provably unused)
// ============================================================
extern "C" void kernel_launch(void* const* d_in, const int* in_sizes, int n_in,
                              void* d_out, int out_size)
{
    const int*   node_ids  = (const int*)d_in[0];
    const int*   neigh_ids = (const int*)d_in[1];
    const float* feat      = (const float*)d_in[2];
    const float* Wq        = (const float*)d_in[3];
    const float* bq        = (const float*)d_in[4];
    const float* Wk        = (const float*)d_in[5];
    const float* Wv        = (const float*)d_in[7];
    const float* bv        = (const float*)d_in[8];
    float*       out       = (float*)d_out;

    int N = in_sizes[0];
    if (N > MAXN) N = MAXN;

    int gblocks = (N + MTILE - 1) / MTILE;
    int ablocks = (N + 7) / 8;
    int xblocks = (N * 64 + 255) / 256;

    prep_xsplit_kernel<<<xblocks + 2 * D + 1, 256>>>(node_ids, feat, Wq, bq, Wk, Wv,
                                                     N, xblocks);
    mma_gemm<0><<<gblocks, 256>>>(nullptr, nullptr, N);
    attn_kernel<<<ablocks, 256>>>(node_ids, neigh_ids, feat, N);
    mma_gemm<1><<<gblocks, 256>>>(bv, out, N);
}

// round 15
// speedup vs baseline: 1.1434x; 1.0670x over previous
#include <cuda_runtime.h>
#include <cuda_bf16.h>
#include <math.h>

#define D     256
#define S     32
#define CTX   33
#define MAXN  20000
#define MAXP  20032      // padded row count
#define MTILE 80         // 5 m-tiles of 16; 250x80 = 20000 exactly

typedef unsigned long long ull;

// ---- device scratch ----
__device__ __align__(16) float g_q[D];                 // Wk^T bq
__device__ __align__(16) float g_Qt[MAXN * D];
// X operands pre-split to bf16 hi/lo
__device__ __align__(16) __nv_bfloat16 g_X0h[MAXP * D];
__device__ __align__(16) __nv_bfloat16 g_X0l[MAXP * D];
__device__ __align__(16) __nv_bfloat16 g_X1h[MAXP * D];
__device__ __align__(16) __nv_bfloat16 g_X1l[MAXP * D];
// B matrices, bf16 hi/lo splits, [k][n] row-major
__device__ __align__(16) __nv_bfloat16 g_B0h[D * D];   // split of Wq^T Wk
__device__ __align__(16) __nv_bfloat16 g_B0l[D * D];
__device__ __align__(16) __nv_bfloat16 g_B1h[D * D];   // split of Wv^T
__device__ __align__(16) __nv_bfloat16 g_B1l[D * D];

__device__ __forceinline__ void bsplit(float x, __nv_bfloat16& h, __nv_bfloat16& l) {
    h = __float2bfloat16(x);
    l = __float2bfloat16(x - __bfloat162float(h));
}
__device__ __forceinline__ unsigned sptr(const void* p) {
    return (unsigned)__cvta_generic_to_shared(p);
}
__device__ __forceinline__ void cp16(void* smem_dst, const void* gsrc) {
    unsigned s = sptr(smem_dst);
    asm volatile("cp.async.cg.shared.global [%0], [%1], 16;" :: "r"(s), "l"(gsrc));
}
__device__ __forceinline__ unsigned packbf(__nv_bfloat16 a, __nv_bfloat16 b) {
    return (unsigned)__bfloat16_as_ushort(a) | ((unsigned)__bfloat16_as_ushort(b) << 16);
}
// 256-bit evict_last gather: 8 floats per lane (sm_103 requires v4.b64 for evict_last)
__device__ __forceinline__ void ldg_el8(const float* p, float4& a, float4& b) {
    ull r0, r1, r2, r3;
    asm volatile("ld.global.nc.L2::evict_last.v4.u64 {%0,%1,%2,%3}, [%4];"
                 : "=l"(r0), "=l"(r1), "=l"(r2), "=l"(r3) : "l"(p));
    a.x = __uint_as_float((unsigned)r0); a.y = __uint_as_float((unsigned)(r0 >> 32));
    a.z = __uint_as_float((unsigned)r1); a.w = __uint_as_float((unsigned)(r1 >> 32));
    b.x = __uint_as_float((unsigned)r2); b.y = __uint_as_float((unsigned)(r2 >> 32));
    b.z = __uint_as_float((unsigned)r3); b.w = __uint_as_float((unsigned)(r3 >> 32));
}

#define MMA_BF16(ac, A, B0, B1)                                              \
    asm volatile("mma.sync.aligned.m16n8k16.row.col.f32.bf16.bf16.f32 "      \
                 "{%0,%1,%2,%3},{%4,%5,%6,%7},{%8,%9},{%0,%1,%2,%3};"        \
                 : "+f"(ac[0]), "+f"(ac[1]), "+f"(ac[2]), "+f"(ac[3])        \
                 : "r"(A[0]), "r"(A[1]), "r"(A[2]), "r"(A[3]),               \
                   "r"(B0), "r"(B1))

// ============================================================
// prep + xsplit merged. xsplit: one thread = 8 floats (32B, evict_last).
// ============================================================
__global__ void prep_xsplit_kernel(const int* __restrict__ node_ids,
                                   const float* __restrict__ feat,
                                   const float* __restrict__ Wq,
                                   const float* __restrict__ bq,
                                   const float* __restrict__ Wk,
                                   const float* __restrict__ Wv,
                                   int N, int xblocks)
{
    __shared__ __align__(16) float sv[D];
    int t = threadIdx.x;

    if (blockIdx.x < (unsigned)xblocks) {
        int idx = blockIdx.x * 256 + t;
        int row = idx >> 5;            // 32 threads per row
        if (row >= N) return;
        int col = (idx & 31) * 8;
        float4 va, vb;
        ldg_el8(feat + (size_t)node_ids[row] * D + col, va, vb);
        __nv_bfloat16 h[8], l[8];
        bsplit(va.x, h[0], l[0]); bsplit(va.y, h[1], l[1]);
        bsplit(va.z, h[2], l[2]); bsplit(va.w, h[3], l[3]);
        bsplit(vb.x, h[4], l[4]); bsplit(vb.y, h[5], l[5]);
        bsplit(vb.z, h[6], l[6]); bsplit(vb.w, h[7], l[7]);
        uint4 ph = {packbf(h[0], h[1]), packbf(h[2], h[3]),
                    packbf(h[4], h[5]), packbf(h[6], h[7])};
        uint4 pl = {packbf(l[0], l[1]), packbf(l[2], l[3]),
                    packbf(l[4], l[5]), packbf(l[6], l[7])};
        *(uint4*)(g_X0h + (size_t)row * D + col) = ph;
        *(uint4*)(g_X0l + (size_t)row * D + col) = pl;
        return;
    }

    int b = blockIdx.x - xblocks;
    if (b < D) {
        sv[t] = Wq[t * D + b];
        __syncthreads();
        float acc = 0.f;
        #pragma unroll 8
        for (int d = 0; d < D; d++) acc += sv[d] * Wk[d * D + t];
        __nv_bfloat16 h, l;
        bsplit(acc, h, l);
        g_B0h[b * D + t] = h;
        g_B0l[b * D + t] = l;
    } else if (b == D) {
        sv[t] = bq[t];
        __syncthreads();
        float acc = 0.f;
        #pragma unroll 8
        for (int d = 0; d < D; d++) acc += sv[d] * Wk[d * D + t];
        g_q[t] = acc;
    } else {
        int dd = b - (D + 1);
        float v = Wv[dd * D + t];
        __nv_bfloat16 h, l;
        bsplit(v, h, l);
        g_B1h[t * D + dd] = h;
        g_B1l[t * D + dd] = l;
    }
}

// ============================================================
// Tensor-core GEMM, bf16-split 3-MMA compensation.
// MTILE=80 (5 m-tiles), grid = 250 -> SINGLE WAVE.
// Warp w owns all 5 m-tiles x 32-col slice [w*32, w*32+32).
// MODE 0: A = g_X0*, B = B0, bias = g_q            -> g_Qt
// MODE 1: A = g_X1*, B = B1, bias = bv, tanh+norm  -> out
// ============================================================
template <int MODE>
__global__ __launch_bounds__(256, 2)
void mma_gemm(const float* __restrict__ bias_in,
              float* __restrict__ outp,
              int N)
{
    __shared__ __align__(16) __nv_bfloat16 sBh[2][16 * 256];  // swizzled
    __shared__ __align__(16) __nv_bfloat16 sBl[2][16 * 256];
    __shared__ __align__(16) __nv_bfloat16 sAh[2][MTILE * 24];
    __shared__ __align__(16) __nv_bfloat16 sAl[2][MTILE * 24];
    __shared__ float sRS[MTILE][8];

    const int tid  = threadIdx.x;
    const int lane = tid & 31;
    const int warp = tid >> 5;              // n-slice owner (32 cols)
    const int m0   = blockIdx.x * MTILE;

    const __nv_bfloat16* gBh = (MODE == 0) ? g_B0h : g_B1h;
    const __nv_bfloat16* gBl = (MODE == 0) ? g_B0l : g_B1l;
    const __nv_bfloat16* gXh = (MODE == 0) ? g_X0h : g_X1h;
    const __nv_bfloat16* gXl = (MODE == 0) ? g_X0l : g_X1l;

    // A copy: 80 rows x 2 halves x 2 splits = 320 16B units
    auto copyA = [&](int buf, int c, int u) {
        int asp   = (u >= 160) ? 1 : 0;
        int rem   = u - asp * 160;
        int ar    = rem >> 1;
        int ahalf = rem & 1;
        int row   = m0 + ar;
        if (row >= N) row = N - 1;
        const __nv_bfloat16* src = (asp ? gXl : gXh)
                                   + (size_t)row * D + c * 16 + ahalf * 8;
        __nv_bfloat16* dst = (asp ? sAl[buf] : sAh[buf]) + ar * 24 + ahalf * 8;
        cp16(dst, src);
    };

    auto issue = [&](int buf, int c) {
        #pragma unroll
        for (int j = 0; j < 2; j++) {
            int gi = tid + j * 256;
            int k  = gi >> 5, cn = gi & 31;
            int dc = cn ^ (k & 7);
            cp16(&sBh[buf][k * 256 + dc * 8], gBh + c * 4096 + k * 256 + cn * 8);
            cp16(&sBl[buf][k * 256 + dc * 8], gBl + c * 4096 + k * 256 + cn * 8);
        }
        copyA(buf, c, tid);
        if (tid < 64) copyA(buf, c, tid + 256);
        asm volatile("cp.async.commit_group;");
    };

    float acc[5][4][4];
    #pragma unroll
    for (int mt = 0; mt < 5; mt++)
        #pragma unroll
        for (int t = 0; t < 4; t++)
            #pragma unroll
            for (int j = 0; j < 4; j++) acc[mt][t][j] = 0.f;

    issue(0, 0);

    const int arow = lane & 15, asel = (lane >> 4) & 1;
    const int krow = lane & 15, bsel = (lane >> 4) & 1;

    #pragma unroll 1
    for (int c = 0; c < 16; c++) {
        int buf = c & 1;
        asm volatile("cp.async.wait_group 0;");
        __syncthreads();          // single barrier per chunk
        if (c < 15) issue(buf ^ 1, c + 1);

        // B fragments for this warp's 32 cols: p = 0,1 (16 cols each)
        unsigned bh[2][4], bl[2][4];
        #pragma unroll
        for (int p = 0; p < 2; p++) {
            int cn = warp * 4 + p * 2 + bsel;
            int bofs = krow * 256 + ((cn ^ (krow & 7)) << 3);
            unsigned addr = sptr(&sBh[buf][bofs]);
            asm volatile("ldmatrix.sync.aligned.m8n8.x4.trans.shared.b16 {%0,%1,%2,%3},[%4];"
                         : "=r"(bh[p][0]), "=r"(bh[p][1]), "=r"(bh[p][2]), "=r"(bh[p][3]) : "r"(addr));
            addr = sptr(&sBl[buf][bofs]);
            asm volatile("ldmatrix.sync.aligned.m8n8.x4.trans.shared.b16 {%0,%1,%2,%3},[%4];"
                         : "=r"(bl[p][0]), "=r"(bl[p][1]), "=r"(bl[p][2]), "=r"(bl[p][3]) : "r"(addr));
        }

        #pragma unroll
        for (int mt = 0; mt < 5; mt++) {
            unsigned ah[4], al[4];
            unsigned addr = sptr(&sAh[buf][(mt * 16 + arow) * 24 + asel * 8]);
            asm volatile("ldmatrix.sync.aligned.m8n8.x4.shared.b16 {%0,%1,%2,%3},[%4];"
                         : "=r"(ah[0]), "=r"(ah[1]), "=r"(ah[2]), "=r"(ah[3]) : "r"(addr));
            addr = sptr(&sAl[buf][(mt * 16 + arow) * 24 + asel * 8]);
            asm volatile("ldmatrix.sync.aligned.m8n8.x4.shared.b16 {%0,%1,%2,%3},[%4];"
                         : "=r"(al[0]), "=r"(al[1]), "=r"(al[2]), "=r"(al[3]) : "r"(addr));
            #pragma unroll
            for (int p = 0; p < 2; p++) {
                MMA_BF16(acc[mt][2 * p],     ah, bh[p][0], bh[p][1]);
                MMA_BF16(acc[mt][2 * p],     ah, bl[p][0], bl[p][1]);
                MMA_BF16(acc[mt][2 * p],     al, bh[p][0], bh[p][1]);
                MMA_BF16(acc[mt][2 * p + 1], ah, bh[p][2], bh[p][3]);
                MMA_BF16(acc[mt][2 * p + 1], ah, bl[p][2], bl[p][3]);
                MMA_BF16(acc[mt][2 * p + 1], al, bh[p][2], bh[p][3]);
            }
        }
    }

    // ---- epilogue: warp owns cols [warp*32, +32), all 80 rows ----
    const float* bias = (MODE == 0) ? g_q : bias_in;
    const int g   = lane >> 2;
    const int tig = lane & 3;

    #pragma unroll
    for (int mt = 0; mt < 5; mt++)
        #pragma unroll
        for (int t = 0; t < 4; t++) {
            int col = warp * 32 + t * 8 + tig * 2;
            float bx = bias[col], by = bias[col + 1];
            acc[mt][t][0] += bx; acc[mt][t][1] += by;
            acc[mt][t][2] += bx; acc[mt][t][3] += by;
        }

    if (MODE == 0) {
        #pragma unroll
        for (int mt = 0; mt < 5; mt++) {
            int row0 = m0 + mt * 16 + g;
            int row1 = row0 + 8;
            #pragma unroll
            for (int t = 0; t < 4; t++) {
                int col = warp * 32 + t * 8 + tig * 2;
                if (row0 < N) {
                    float2 o = {acc[mt][t][0], acc[mt][t][1]};
                    *(float2*)(g_Qt + (size_t)row0 * D + col) = o;
                }
                if (row1 < N) {
                    float2 o = {acc[mt][t][2], acc[mt][t][3]};
                    *(float2*)(g_Qt + (size_t)row1 * D + col) = o;
                }
            }
        }
    } else {
        // tanh, then cross-warp row L2 norm (each row spans 8 warps)
        #pragma unroll
        for (int mt = 0; mt < 5; mt++) {
            float s0 = 0.f, s1 = 0.f;
            #pragma unroll
            for (int t = 0; t < 4; t++) {
                #pragma unroll
                for (int j = 0; j < 4; j++) acc[mt][t][j] = tanhf(acc[mt][t][j]);
                s0 += acc[mt][t][0] * acc[mt][t][0] + acc[mt][t][1] * acc[mt][t][1];
                s1 += acc[mt][t][2] * acc[mt][t][2] + acc[mt][t][3] * acc[mt][t][3];
            }
            s0 += __shfl_xor_sync(0xFFFFFFFFu, s0, 1);
            s0 += __shfl_xor_sync(0xFFFFFFFFu, s0, 2);
            s1 += __shfl_xor_sync(0xFFFFFFFFu, s1, 1);
            s1 += __shfl_xor_sync(0xFFFFFFFFu, s1, 2);
            if (tig == 0) {
                sRS[mt * 16 + g][warp]     = s0;
                sRS[mt * 16 + g + 8][warp] = s1;
            }
        }
        __syncthreads();
        #pragma unroll
        for (int mt = 0; mt < 5; mt++) {
            int r0 = mt * 16 + g;
            int r1 = r0 + 8;
            float t0 = 0.f, t1 = 0.f;
            #pragma unroll
            for (int w = 0; w < 8; w++) { t0 += sRS[r0][w]; t1 += sRS[r1][w]; }
            float inv0 = 1.f / fmaxf(sqrtf(t0), 1e-12f);
            float inv1 = 1.f / fmaxf(sqrtf(t1), 1e-12f);
            int row0 = m0 + r0, row1 = m0 + r1;
            #pragma unroll
            for (int t = 0; t < 4; t++) {
                int col = warp * 32 + t * 8 + tig * 2;
                if (row0 < N) {
                    float2 o = {acc[mt][t][0] * inv0, acc[mt][t][1] * inv0};
                    *(float2*)(outp + (size_t)row0 * D + col) = o;
                }
                if (row1 < N) {
                    float2 o = {acc[mt][t][2] * inv1, acc[mt][t][3] * inv1};
                    *(float2*)(outp + (size_t)row1 * D + col) = o;
                }
            }
        }
    }
}

// ============================================================
// attention: one warp per node, PAIRED online softmax.
// Lane owns cols [lane*8, lane*8+8): ONE 256-bit evict_last
// LDG per ctx row per lane. Output pre-split bf16 hi/lo.
// ============================================================
__global__ __launch_bounds__(256)
void attn_kernel(const int* __restrict__ node_ids,
                 const int* __restrict__ neigh_ids,
                 const float* __restrict__ feat,
                 int N)
{
    const int warp = threadIdx.x >> 5;
    const int lane = threadIdx.x & 31;
    const int n    = blockIdx.x * 8 + warp;
    if (n >= N) return;

    // q fragment: contiguous 8 floats at lane*8
    const float4* qt4 = (const float4*)(g_Qt + (size_t)n * D);
    float4 qa = qt4[lane * 2];
    float4 qb = qt4[lane * 2 + 1];

    int id_l = neigh_ids[(size_t)n * S + lane];

    auto rowptr = [&](int r) -> const float* {
        int id = (r == 0) ? node_ids[n] : __shfl_sync(0xFFFFFFFFu, id_l, r - 1);
        return feat + (size_t)id * D + lane * 8;
    };

    float4 c0a, c0b, c1a, c1b, n0a, n0b, n1a, n1b;
    ldg_el8(rowptr(0), c0a, c0b);
    ldg_el8(rowptr(1), c1a, c1b);
    ldg_el8(rowptr(2), n0a, n0b);
    ldg_el8(rowptr(3), n1a, n1b);

    float m = -3.0e38f, s = 0.f;
    float4 aa = {0.f, 0.f, 0.f, 0.f};
    float4 ab = {0.f, 0.f, 0.f, 0.f};

    #pragma unroll 1
    for (int pr = 0; pr < 16; pr++) {          // pairs cover rows 0..31
        int r2 = 2 * pr + 4, r3 = 2 * pr + 5;
        float4 t0a, t0b, t1a, t1b;
        if (r2 < CTX) ldg_el8(rowptr(r2), t0a, t0b);
        if (r3 < CTX) ldg_el8(rowptr(r3), t1a, t1b);

        float d0 = c0a.x * qa.x + c0a.y * qa.y + c0a.z * qa.z + c0a.w * qa.w
                 + c0b.x * qb.x + c0b.y * qb.y + c0b.z * qb.z + c0b.w * qb.w;
        float d1 = c1a.x * qa.x + c1a.y * qa.y + c1a.z * qa.z + c1a.w * qa.w
                 + c1b.x * qb.x + c1b.y * qb.y + c1b.z * qb.z + c1b.w * qb.w;
        #pragma unroll
        for (int o = 16; o > 0; o >>= 1) {     // two independent trees
            d0 += __shfl_xor_sync(0xFFFFFFFFu, d0, o);
            d1 += __shfl_xor_sync(0xFFFFFFFFu, d1, o);
        }

        float mn = fmaxf(m, fmaxf(d0, d1));
        float sc = __expf(m - mn);
        float e0 = __expf(d0 - mn);
        float e1 = __expf(d1 - mn);
        s = s * sc + e0 + e1;
        aa.x = aa.x * sc + e0 * c0a.x + e1 * c1a.x;
        aa.y = aa.y * sc + e0 * c0a.y + e1 * c1a.y;
        aa.z = aa.z * sc + e0 * c0a.z + e1 * c1a.z;
        aa.w = aa.w * sc + e0 * c0a.w + e1 * c1a.w;
        ab.x = ab.x * sc + e0 * c0b.x + e1 * c1b.x;
        ab.y = ab.y * sc + e0 * c0b.y + e1 * c1b.y;
        ab.z = ab.z * sc + e0 * c0b.z + e1 * c1b.z;
        ab.w = ab.w * sc + e0 * c0b.w + e1 * c1b.w;
        m = mn;
        c0a = n0a; c0b = n0b; c1a = n1a; c1b = n1b;
        n0a = t0a; n0b = t0b; n1a = t1a; n1b = t1b;
    }

    // tail: row 32 is in (c0a, c0b)
    {
        float d = c0a.x * qa.x + c0a.y * qa.y + c0a.z * qa.z + c0a.w * qa.w
                + c0b.x * qb.x + c0b.y * qb.y + c0b.z * qb.z + c0b.w * qb.w;
        #pragma unroll
        for (int o = 16; o > 0; o >>= 1)
            d += __shfl_xor_sync(0xFFFFFFFFu, d, o);
        float mn = fmaxf(m, d);
        float sc = __expf(m - mn);
        float e  = __expf(d - mn);
        s = s * sc + e;
        aa.x = aa.x * sc + e * c0a.x;  aa.y = aa.y * sc + e * c0a.y;
        aa.z = aa.z * sc + e * c0a.z;  aa.w = aa.w * sc + e * c0a.w;
        ab.x = ab.x * sc + e * c0b.x;  ab.y = ab.y * sc + e * c0b.y;
        ab.z = ab.z * sc + e * c0b.z;  ab.w = ab.w * sc + e * c0b.w;
    }

    float inv = 1.f / s;
    float v[8] = {aa.x * inv, aa.y * inv, aa.z * inv, aa.w * inv,
                  ab.x * inv, ab.y * inv, ab.z * inv, ab.w * inv};

    // lane owns 8 contiguous cols -> one uint4 store per split
    __nv_bfloat16 h[8], l[8];
    #pragma unroll
    for (int j = 0; j < 8; j++) bsplit(v[j], h[j], l[j]);
    uint4 ph = {packbf(h[0], h[1]), packbf(h[2], h[3]),
                packbf(h[4], h[5]), packbf(h[6], h[7])};
    uint4 pl = {packbf(l[0], l[1]), packbf(l[2], l[3]),
                packbf(l[4], l[5]), packbf(l[6], l[7])};
    size_t base = (size_t)n * D + lane * 8;
    *(uint4*)(g_X1h + base) = ph;
    *(uint4*)(g_X1l + base) = pl;
}

// ============================================================
// inputs: node_ids, neigh_ids, feat_table, Wq, bq, Wk, bk, Wv, bv
// (bk only enters softmax-invariant terms -> provably unused)
// ============================================================
extern "C" void kernel_launch(void* const* d_in, const int* in_sizes, int n_in,
                              void* d_out, int out_size)
{
    const int*   node_ids  = (const int*)d_in[0];
    const int*   neigh_ids = (const int*)d_in[1];
    const float* feat      = (const float*)d_in[2];
    const float* Wq        = (const float*)d_in[3];
    const float* bq        = (const float*)d_in[4];
    const float* Wk        = (const float*)d_in[5];
    const float* Wv        = (const float*)d_in[7];
    const float* bv        = (const float*)d_in[8];
    float*       out       = (float*)d_out;

    int N = in_sizes[0];
    if (N > MAXN) N = MAXN;

    int gblocks = (N + MTILE - 1) / MTILE;     // 250 for N=20000
    int ablocks = (N + 7) / 8;
    int xblocks = (N * 32 + 255) / 256;        // 32 threads per row now

    prep_xsplit_kernel<<<xblocks + 2 * D + 1, 256>>>(node_ids, feat, Wq, bq, Wk, Wv,
                                                     N, xblocks);
    mma_gemm<0><<<gblocks, 256>>>(nullptr, nullptr, N);
    attn_kernel<<<ablocks, 256>>>(node_ids, neigh_ids, feat, N);
    mma_gemm<1><<<gblocks, 256>>>(bv, out, N);
}

// round 16
// speedup vs baseline: 1.1437x; 1.0002x over previous
#include <cuda_runtime.h>
#include <cuda_bf16.h>
#include <math.h>

#define D     256
#define S     32
#define CTX   33
#define MAXN  20000
#define MAXP  20032      // padded row count
#define MTILE 80         // 5 m-tiles of 16; 250x80 = 20000 exactly
#define NST   3          // pipeline stages

typedef unsigned long long ull;

// ---- device scratch ----
__device__ __align__(16) float g_q[D];                 // Wk^T bq
__device__ __align__(16) float g_Qt[MAXN * D];
// X operands pre-split to bf16 hi/lo
__device__ __align__(16) __nv_bfloat16 g_X0h[MAXP * D];
__device__ __align__(16) __nv_bfloat16 g_X0l[MAXP * D];
__device__ __align__(16) __nv_bfloat16 g_X1h[MAXP * D];
__device__ __align__(16) __nv_bfloat16 g_X1l[MAXP * D];
// B matrices, bf16 hi/lo splits, [k][n] row-major
__device__ __align__(16) __nv_bfloat16 g_B0h[D * D];   // split of Wq^T Wk
__device__ __align__(16) __nv_bfloat16 g_B0l[D * D];
__device__ __align__(16) __nv_bfloat16 g_B1h[D * D];   // split of Wv^T
__device__ __align__(16) __nv_bfloat16 g_B1l[D * D];

// dynamic smem layout (bf16 elements / bytes)
#define SB_ELEMS   (16 * 256)                  // per stage per split
#define SA_ELEMS   (MTILE * 24)
#define OFF_BH(st) ((st) * SB_ELEMS)
#define OFF_BL(st) ((NST + (st)) * SB_ELEMS)
#define OFF_AH(st) (2 * NST * SB_ELEMS + (st) * SA_ELEMS)
#define OFF_AL(st) (2 * NST * SB_ELEMS + (NST + (st)) * SA_ELEMS)
#define OFF_RS     (2 * NST * SB_ELEMS + 2 * NST * SA_ELEMS)   // float[80][8]
#define SMEM_BYTES (OFF_RS * 2 + MTILE * 8 * 4)

__device__ __forceinline__ void bsplit(float x, __nv_bfloat16& h, __nv_bfloat16& l) {
    h = __float2bfloat16(x);
    l = __float2bfloat16(x - __bfloat162float(h));
}
__device__ __forceinline__ unsigned sptr(const void* p) {
    return (unsigned)__cvta_generic_to_shared(p);
}
__device__ __forceinline__ void cp16(void* smem_dst, const void* gsrc) {
    unsigned s = sptr(smem_dst);
    asm volatile("cp.async.cg.shared.global [%0], [%1], 16;" :: "r"(s), "l"(gsrc));
}
__device__ __forceinline__ unsigned packbf(__nv_bfloat16 a, __nv_bfloat16 b) {
    return (unsigned)__bfloat16_as_ushort(a) | ((unsigned)__bfloat16_as_ushort(b) << 16);
}
// 256-bit evict_last gather: 8 floats per lane
__device__ __forceinline__ void ldg_el8(const float* p, float4& a, float4& b) {
    ull r0, r1, r2, r3;
    asm volatile("ld.global.nc.L2::evict_last.v4.u64 {%0,%1,%2,%3}, [%4];"
                 : "=l"(r0), "=l"(r1), "=l"(r2), "=l"(r3) : "l"(p));
    a.x = __uint_as_float((unsigned)r0); a.y = __uint_as_float((unsigned)(r0 >> 32));
    a.z = __uint_as_float((unsigned)r1); a.w = __uint_as_float((unsigned)(r1 >> 32));
    b.x = __uint_as_float((unsigned)r2); b.y = __uint_as_float((unsigned)(r2 >> 32));
    b.z = __uint_as_float((unsigned)r3); b.w = __uint_as_float((unsigned)(r3 >> 32));
}

#define MMA_BF16(ac, A, B0, B1)                                              \
    asm volatile("mma.sync.aligned.m16n8k16.row.col.f32.bf16.bf16.f32 "      \
                 "{%0,%1,%2,%3},{%4,%5,%6,%7},{%8,%9},{%0,%1,%2,%3};"        \
                 : "+f"(ac[0]), "+f"(ac[1]), "+f"(ac[2]), "+f"(ac[3])        \
                 : "r"(A[0]), "r"(A[1]), "r"(A[2]), "r"(A[3]),               \
                   "r"(B0), "r"(B1))

// ============================================================
// prep + xsplit merged. xsplit: one thread = 8 floats (32B, evict_last).
// ============================================================
__global__ void prep_xsplit_kernel(const int* __restrict__ node_ids,
                                   const float* __restrict__ feat,
                                   const float* __restrict__ Wq,
                                   const float* __restrict__ bq,
                                   const float* __restrict__ Wk,
                                   const float* __restrict__ Wv,
                                   int N, int xblocks)
{
    __shared__ __align__(16) float sv[D];
    int t = threadIdx.x;

    if (blockIdx.x < (unsigned)xblocks) {
        int idx = blockIdx.x * 256 + t;
        int row = idx >> 5;
        if (row >= N) return;
        int col = (idx & 31) * 8;
        float4 va, vb;
        ldg_el8(feat + (size_t)node_ids[row] * D + col, va, vb);
        __nv_bfloat16 h[8], l[8];
        bsplit(va.x, h[0], l[0]); bsplit(va.y, h[1], l[1]);
        bsplit(va.z, h[2], l[2]); bsplit(va.w, h[3], l[3]);
        bsplit(vb.x, h[4], l[4]); bsplit(vb.y, h[5], l[5]);
        bsplit(vb.z, h[6], l[6]); bsplit(vb.w, h[7], l[7]);
        uint4 ph = {packbf(h[0], h[1]), packbf(h[2], h[3]),
                    packbf(h[4], h[5]), packbf(h[6], h[7])};
        uint4 pl = {packbf(l[0], l[1]), packbf(l[2], l[3]),
                    packbf(l[4], l[5]), packbf(l[6], l[7])};
        *(uint4*)(g_X0h + (size_t)row * D + col) = ph;
        *(uint4*)(g_X0l + (size_t)row * D + col) = pl;
        return;
    }

    int b = blockIdx.x - xblocks;
    if (b < D) {
        sv[t] = Wq[t * D + b];
        __syncthreads();
        float acc = 0.f;
        #pragma unroll 8
        for (int d = 0; d < D; d++) acc += sv[d] * Wk[d * D + t];
        __nv_bfloat16 h, l;
        bsplit(acc, h, l);
        g_B0h[b * D + t] = h;
        g_B0l[b * D + t] = l;
    } else if (b == D) {
        sv[t] = bq[t];
        __syncthreads();
        float acc = 0.f;
        #pragma unroll 8
        for (int d = 0; d < D; d++) acc += sv[d] * Wk[d * D + t];
        g_q[t] = acc;
    } else {
        int dd = b - (D + 1);
        float v = Wv[dd * D + t];
        __nv_bfloat16 h, l;
        bsplit(v, h, l);
        g_B1h[t * D + dd] = h;
        g_B1l[t * D + dd] = l;
    }
}

// ============================================================
// Tensor-core GEMM, bf16-split 3-MMA compensation.
// MTILE=80, grid=250 single wave; 3-STAGE cp.async pipeline,
// wait_group 1 -> each chunk's copies have 2 compute phases to land.
// Warp w owns all 5 m-tiles x 32-col slice [w*32, w*32+32).
// MODE 0: A = g_X0*, B = B0, bias = g_q            -> g_Qt
// MODE 1: A = g_X1*, B = B1, bias = bv, tanh+norm  -> out
// ============================================================
template <int MODE>
__global__ __launch_bounds__(256, 2)
void mma_gemm(const float* __restrict__ bias_in,
              float* __restrict__ outp,
              int N)
{
    extern __shared__ __align__(16) __nv_bfloat16 smem[];
    float* sRS = (float*)(smem + OFF_RS);      // [MTILE][8]

    const int tid  = threadIdx.x;
    const int lane = tid & 31;
    const int warp = tid >> 5;
    const int m0   = blockIdx.x * MTILE;

    const __nv_bfloat16* gBh = (MODE == 0) ? g_B0h : g_B1h;
    const __nv_bfloat16* gBl = (MODE == 0) ? g_B0l : g_B1l;
    const __nv_bfloat16* gXh = (MODE == 0) ? g_X0h : g_X1h;
    const __nv_bfloat16* gXl = (MODE == 0) ? g_X0l : g_X1l;

    auto copyA = [&](int st, int c, int u) {
        int asp   = (u >= 160) ? 1 : 0;
        int rem   = u - asp * 160;
        int ar    = rem >> 1;
        int ahalf = rem & 1;
        int row   = m0 + ar;
        if (row >= N) row = N - 1;
        const __nv_bfloat16* src = (asp ? gXl : gXh)
                                   + (size_t)row * D + c * 16 + ahalf * 8;
        __nv_bfloat16* dst = smem + (asp ? OFF_AL(st) : OFF_AH(st)) + ar * 24 + ahalf * 8;
        cp16(dst, src);
    };

    auto issue = [&](int st, int c) {
        #pragma unroll
        for (int j = 0; j < 2; j++) {
            int gi = tid + j * 256;
            int k  = gi >> 5, cn = gi & 31;
            int dc = cn ^ (k & 7);
            cp16(smem + OFF_BH(st) + k * 256 + dc * 8, gBh + c * 4096 + k * 256 + cn * 8);
            cp16(smem + OFF_BL(st) + k * 256 + dc * 8, gBl + c * 4096 + k * 256 + cn * 8);
        }
        copyA(st, c, tid);
        if (tid < 64) copyA(st, c, tid + 256);
        asm volatile("cp.async.commit_group;");
    };

    float acc[5][4][4];
    #pragma unroll
    for (int mt = 0; mt < 5; mt++)
        #pragma unroll
        for (int t = 0; t < 4; t++)
            #pragma unroll
            for (int j = 0; j < 4; j++) acc[mt][t][j] = 0.f;

    issue(0, 0);
    issue(1, 1);

    const int arow = lane & 15, asel = (lane >> 4) & 1;
    const int krow = lane & 15, bsel = (lane >> 4) & 1;

    #pragma unroll 1
    for (int c = 0; c < 16; c++) {
        int st = c % NST;
        if (c < 15) asm volatile("cp.async.wait_group 1;");
        else        asm volatile("cp.async.wait_group 0;");
        __syncthreads();          // compute(c-1) finished CTA-wide
        if (c < 14) issue((c + 2) % NST, c + 2);

        const __nv_bfloat16* bh_base = smem + OFF_BH(st);
        const __nv_bfloat16* bl_base = smem + OFF_BL(st);
        const __nv_bfloat16* ahh     = smem + OFF_AH(st);
        const __nv_bfloat16* all_    = smem + OFF_AL(st);

        unsigned bh[2][4], bl[2][4];
        #pragma unroll
        for (int p = 0; p < 2; p++) {
            int cn = warp * 4 + p * 2 + bsel;
            int bofs = krow * 256 + ((cn ^ (krow & 7)) << 3);
            unsigned addr = sptr(bh_base + bofs);
            asm volatile("ldmatrix.sync.aligned.m8n8.x4.trans.shared.b16 {%0,%1,%2,%3},[%4];"
                         : "=r"(bh[p][0]), "=r"(bh[p][1]), "=r"(bh[p][2]), "=r"(bh[p][3]) : "r"(addr));
            addr = sptr(bl_base + bofs);
            asm volatile("ldmatrix.sync.aligned.m8n8.x4.trans.shared.b16 {%0,%1,%2,%3},[%4];"
                         : "=r"(bl[p][0]), "=r"(bl[p][1]), "=r"(bl[p][2]), "=r"(bl[p][3]) : "r"(addr));
        }

        #pragma unroll
        for (int mt = 0; mt < 5; mt++) {
            unsigned ah[4], al[4];
            unsigned addr = sptr(ahh + (mt * 16 + arow) * 24 + asel * 8);
            asm volatile("ldmatrix.sync.aligned.m8n8.x4.shared.b16 {%0,%1,%2,%3},[%4];"
                         : "=r"(ah[0]), "=r"(ah[1]), "=r"(ah[2]), "=r"(ah[3]) : "r"(addr));
            addr = sptr(all_ + (mt * 16 + arow) * 24 + asel * 8);
            asm volatile("ldmatrix.sync.aligned.m8n8.x4.shared.b16 {%0,%1,%2,%3},[%4];"
                         : "=r"(al[0]), "=r"(al[1]), "=r"(al[2]), "=r"(al[3]) : "r"(addr));
            #pragma unroll
            for (int p = 0; p < 2; p++) {
                MMA_BF16(acc[mt][2 * p],     ah, bh[p][0], bh[p][1]);
                MMA_BF16(acc[mt][2 * p],     ah, bl[p][0], bl[p][1]);
                MMA_BF16(acc[mt][2 * p],     al, bh[p][0], bh[p][1]);
                MMA_BF16(acc[mt][2 * p + 1], ah, bh[p][2], bh[p][3]);
                MMA_BF16(acc[mt][2 * p + 1], ah, bl[p][2], bl[p][3]);
                MMA_BF16(acc[mt][2 * p + 1], al, bh[p][2], bh[p][3]);
            }
        }
    }

    // ---- epilogue: warp owns cols [warp*32, +32), all 80 rows ----
    const float* bias = (MODE == 0) ? g_q : bias_in;
    const int g   = lane >> 2;
    const int tig = lane & 3;

    #pragma unroll
    for (int mt = 0; mt < 5; mt++)
        #pragma unroll
        for (int t = 0; t < 4; t++) {
            int col = warp * 32 + t * 8 + tig * 2;
            float bx = bias[col], by = bias[col + 1];
            acc[mt][t][0] += bx; acc[mt][t][1] += by;
            acc[mt][t][2] += bx; acc[mt][t][3] += by;
        }

    if (MODE == 0) {
        #pragma unroll
        for (int mt = 0; mt < 5; mt++) {
            int row0 = m0 + mt * 16 + g;
            int row1 = row0 + 8;
            #pragma unroll
            for (int t = 0; t < 4; t++) {
                int col = warp * 32 + t * 8 + tig * 2;
                if (row0 < N) {
                    float2 o = {acc[mt][t][0], acc[mt][t][1]};
                    *(float2*)(g_Qt + (size_t)row0 * D + col) = o;
                }
                if (row1 < N) {
                    float2 o = {acc[mt][t][2], acc[mt][t][3]};
                    *(float2*)(g_Qt + (size_t)row1 * D + col) = o;
                }
            }
        }
    } else {
        #pragma unroll
        for (int mt = 0; mt < 5; mt++) {
            float s0 = 0.f, s1 = 0.f;
            #pragma unroll
            for (int t = 0; t < 4; t++) {
                #pragma unroll
                for (int j = 0; j < 4; j++) acc[mt][t][j] = tanhf(acc[mt][t][j]);
                s0 += acc[mt][t][0] * acc[mt][t][0] + acc[mt][t][1] * acc[mt][t][1];
                s1 += acc[mt][t][2] * acc[mt][t][2] + acc[mt][t][3] * acc[mt][t][3];
            }
            s0 += __shfl_xor_sync(0xFFFFFFFFu, s0, 1);
            s0 += __shfl_xor_sync(0xFFFFFFFFu, s0, 2);
            s1 += __shfl_xor_sync(0xFFFFFFFFu, s1, 1);
            s1 += __shfl_xor_sync(0xFFFFFFFFu, s1, 2);
            if (tig == 0) {
                sRS[(mt * 16 + g) * 8 + warp]     = s0;
                sRS[(mt * 16 + g + 8) * 8 + warp] = s1;
            }
        }
        __syncthreads();
        #pragma unroll
        for (int mt = 0; mt < 5; mt++) {
            int r0 = mt * 16 + g;
            int r1 = r0 + 8;
            float t0 = 0.f, t1 = 0.f;
            #pragma unroll
            for (int w = 0; w < 8; w++) { t0 += sRS[r0 * 8 + w]; t1 += sRS[r1 * 8 + w]; }
            float inv0 = 1.f / fmaxf(sqrtf(t0), 1e-12f);
            float inv1 = 1.f / fmaxf(sqrtf(t1), 1e-12f);
            int row0 = m0 + r0, row1 = m0 + r1;
            #pragma unroll
            for (int t = 0; t < 4; t++) {
                int col = warp * 32 + t * 8 + tig * 2;
                if (row0 < N) {
                    float2 o = {acc[mt][t][0] * inv0, acc[mt][t][1] * inv0};
                    *(float2*)(outp + (size_t)row0 * D + col) = o;
                }
                if (row1 < N) {
                    float2 o = {acc[mt][t][2] * inv1, acc[mt][t][3] * inv1};
                    *(float2*)(outp + (size_t)row1 * D + col) = o;
                }
            }
        }
    }
}

// ============================================================
// attention: one warp per node, PAIRED online softmax.
// Lane owns cols [lane*8, +8): ONE 256-bit evict_last LDG per row.
// Output pre-split bf16 hi/lo.
// ============================================================
__global__ __launch_bounds__(256)
void attn_kernel(const int* __restrict__ node_ids,
                 const int* __restrict__ neigh_ids,
                 const float* __restrict__ feat,
                 int N)
{
    const int warp = threadIdx.x >> 5;
    const int lane = threadIdx.x & 31;
    const int n    = blockIdx.x * 8 + warp;
    if (n >= N) return;

    const float4* qt4 = (const float4*)(g_Qt + (size_t)n * D);
    float4 qa = qt4[lane * 2];
    float4 qb = qt4[lane * 2 + 1];

    int id_l = neigh_ids[(size_t)n * S + lane];

    auto rowptr = [&](int r) -> const float* {
        int id = (r == 0) ? node_ids[n] : __shfl_sync(0xFFFFFFFFu, id_l, r - 1);
        return feat + (size_t)id * D + lane * 8;
    };

    float4 c0a, c0b, c1a, c1b, n0a, n0b, n1a, n1b;
    ldg_el8(rowptr(0), c0a, c0b);
    ldg_el8(rowptr(1), c1a, c1b);
    ldg_el8(rowptr(2), n0a, n0b);
    ldg_el8(rowptr(3), n1a, n1b);

    float m = -3.0e38f, s = 0.f;
    float4 aa = {0.f, 0.f, 0.f, 0.f};
    float4 ab = {0.f, 0.f, 0.f, 0.f};

    #pragma unroll 1
    for (int pr = 0; pr < 16; pr++) {
        int r2 = 2 * pr + 4, r3 = 2 * pr + 5;
        float4 t0a, t0b, t1a, t1b;
        if (r2 < CTX) ldg_el8(rowptr(r2), t0a, t0b);
        if (r3 < CTX) ldg_el8(rowptr(r3), t1a, t1b);

        float d0 = c0a.x * qa.x + c0a.y * qa.y + c0a.z * qa.z + c0a.w * qa.w
                 + c0b.x * qb.x + c0b.y * qb.y + c0b.z * qb.z + c0b.w * qb.w;
        float d1 = c1a.x * qa.x + c1a.y * qa.y + c1a.z * qa.z + c1a.w * qa.w
                 + c1b.x * qb.x + c1b.y * qb.y + c1b.z * qb.z + c1b.w * qb.w;
        #pragma unroll
        for (int o = 16; o > 0; o >>= 1) {
            d0 += __shfl_xor_sync(0xFFFFFFFFu, d0, o);
            d1 += __shfl_xor_sync(0xFFFFFFFFu, d1, o);
        }

        float mn = fmaxf(m, fmaxf(d0, d1));
        float sc = __expf(m - mn);
        float e0 = __expf(d0 - mn);
        float e1 = __expf(d1 - mn);
        s = s * sc + e0 + e1;
        aa.x = aa.x * sc + e0 * c0a.x + e1 * c1a.x;
        aa.y = aa.y * sc + e0 * c0a.y + e1 * c1a.y;
        aa.z = aa.z * sc + e0 * c0a.z + e1 * c1a.z;
        aa.w = aa.w * sc + e0 * c0a.w + e1 * c1a.w;
        ab.x = ab.x * sc + e0 * c0b.x + e1 * c1b.x;
        ab.y = ab.y * sc + e0 * c0b.y + e1 * c1b.y;
        ab.z = ab.z * sc + e0 * c0b.z + e1 * c1b.z;
        ab.w = ab.w * sc + e0 * c0b.w + e1 * c1b.w;
        m = mn;
        c0a = n0a; c0b = n0b; c1a = n1a; c1b = n1b;
        n0a = t0a; n0b = t0b; n1a = t1a; n1b = t1b;
    }

    // tail: row 32 is in (c0a, c0b)
    {
        float d = c0a.x * qa.x + c0a.y * qa.y + c0a.z * qa.z + c0a.w * qa.w
                + c0b.x * qb.x + c0b.y * qb.y + c0b.z * qb.z + c0b.w * qb.w;
        #pragma unroll
        for (int o = 16; o > 0; o >>= 1)
            d += __shfl_xor_sync(0xFFFFFFFFu, d, o);
        float mn = fmaxf(m, d);
        float sc = __expf(m - mn);
        float e  = __expf(d - mn);
        s = s * sc + e;
        aa.x = aa.x * sc + e * c0a.x;  aa.y = aa.y * sc + e * c0a.y;
        aa.z = aa.z * sc + e * c0a.z;  aa.w = aa.w * sc + e * c0a.w;
        ab.x = ab.x * sc + e * c0b.x;  ab.y = ab.y * sc + e * c0b.y;
        ab.z = ab.z * sc + e * c0b.z;  ab.w = ab.w * sc + e * c0b.w;
    }

    float inv = 1.f / s;
    float v[8] = {aa.x * inv, aa.y * inv, aa.z * inv, aa.w * inv,
                  ab.x * inv, ab.y * inv, ab.z * inv, ab.w * inv};

    __nv_bfloat16 h[8], l[8];
    #pragma unroll
    for (int j = 0; j < 8; j++) bsplit(v[j], h[j], l[j]);
    uint4 ph = {packbf(h[0], h[1]), packbf(h[2], h[3]),
                packbf(h[4], h[5]), packbf(h[6], h[7])};
    uint4 pl = {packbf(l[0], l[1]), packbf(l[2], l[3]),
                packbf(l[4], l[5]), packbf(l[6], l[7])};
    size_t base = (size_t)n * D + lane * 8;
    *(uint4*)(g_X1h + base) = ph;
    *(uint4*)(g_X1l + base) = pl;
}

// ============================================================
// inputs: node_ids, neigh_ids, feat_table, Wq, bq, Wk, bk, Wv, bv
// (bk only enters softmax-invariant terms -> provably unused)
// ============================================================
extern "C" void kernel_launch(void* const* d_in, const int* in_sizes, int n_in,
                              void* d_out, int out_size)
{
    const int*   node_ids  = (const int*)d_in[0];
    const int*   neigh_ids = (const int*)d_in[1];
    const float* feat      = (const float*)d_in[2];
    const float* Wq        = (const float*)d_in[3];
    const float* bq        = (const float*)d_in[4];
    const float* Wk        = (const float*)d_in[5];
    const float* Wv        = (const float*)d_in[7];
    const float* bv        = (const float*)d_in[8];
    float*       out       = (float*)d_out;

    int N = in_sizes[0];
    if (N > MAXN) N = MAXN;

    int gblocks = (N + MTILE - 1) / MTILE;     // 250 for N=20000
    int ablocks = (N + 7) / 8;
    int xblocks = (N * 32 + 255) / 256;

    cudaFuncSetAttribute(mma_gemm<0>,
                         cudaFuncAttributeMaxDynamicSharedMemorySize, SMEM_BYTES);
    cudaFuncSetAttribute(mma_gemm<1>,
                         cudaFuncAttributeMaxDynamicSharedMemorySize, SMEM_BYTES);

    prep_xsplit_kernel<<<xblocks + 2 * D + 1, 256>>>(node_ids, feat, Wq, bq, Wk, Wv,
                                                     N, xblocks);
    mma_gemm<0><<<gblocks, 256, SMEM_BYTES>>>(nullptr, nullptr, N);
    attn_kernel<<<ablocks, 256>>>(node_ids, neigh_ids, feat, N);
    mma_gemm<1><<<gblocks, 256, SMEM_BYTES>>>(bv, out, N);
}